// round 13
// baseline (speedup 1.0000x reference)
#include <cuda_runtime.h>

#define NN 4096
#define DIM 64
#define INF_V 1e10f
#define NBLK 32           // 32 bands x 128 rows (one warp per band, 4 rows/lane)
#define NTILE 1024        // tile-columns (4 cols each)
#define LOG2E 1.4426950408889634f
#define LN2   0.6931471805599453f

// Scratch (static __device__ arrays: allocation-free per harness rules)
__device__ float g_D[(size_t)NN * NN];    // cost matrix, PRE-SCALED by log2(e)
__device__ float g_xn[NN];
__device__ float g_yn[NN];
__device__ float g_bnd[NBLK][NN];         // bottom boundary row of each band (base-2)
__device__ int   g_prog[NBLK];            // tiles published per band

// ---------------- norms ----------------
__global__ void norms_kernel(const float* __restrict__ x, const float* __restrict__ y) {
    int w = (blockIdx.x * blockDim.x + threadIdx.x) >> 5;
    int lane = threadIdx.x & 31;
    if (w >= 2 * NN) return;
    const float* src = (w < NN) ? x : y;
    int row = (w < NN) ? w : w - NN;
    float a = src[row * DIM + lane];
    float b = src[row * DIM + 32 + lane];
    float s = a * a + b * b;
    #pragma unroll
    for (int o = 16; o; o >>= 1) s += __shfl_xor_sync(0xffffffffu, s, o);
    if (lane == 0) { if (w < NN) g_xn[row] = s; else g_yn[row] = s; }
}

// ---------------- D2 = (|x|^2 + |y|^2 - 2 x.y) * log2(e) ----------------
__global__ void dmat_kernel(const float* __restrict__ x, const float* __restrict__ y) {
    __shared__ float xs[64][65];
    __shared__ float ys[64][65];
    int tx = threadIdx.x, ty = threadIdx.y;
    int tid = ty * 16 + tx;
    int rb = blockIdx.y * 64, cb = blockIdx.x * 64;

    for (int i = tid; i < 64 * 64; i += 256) {
        int rr = i >> 6, kk = i & 63;
        xs[rr][kk] = x[(rb + rr) * DIM + kk];
        ys[rr][kk] = y[(cb + rr) * DIM + kk];
    }
    __syncthreads();

    float acc[4][4] = {};
    #pragma unroll
    for (int k = 0; k < 64; k++) {
        float xv[4], yv[4];
        #pragma unroll
        for (int i = 0; i < 4; i++) xv[i] = xs[ty + 16 * i][k];
        #pragma unroll
        for (int j = 0; j < 4; j++) yv[j] = ys[tx + 16 * j][k];
        #pragma unroll
        for (int i = 0; i < 4; i++)
            #pragma unroll
            for (int j = 0; j < 4; j++)
                acc[i][j] += xv[i] * yv[j];
    }

    #pragma unroll
    for (int i = 0; i < 4; i++) {
        int r = rb + ty + 16 * i;
        float xnr = g_xn[r];
        #pragma unroll
        for (int j = 0; j < 4; j++) {
            int c = cb + tx + 16 * j;
            g_D[(size_t)r * NN + c] = (xnr + g_yn[c] - 2.0f * acc[i][j]) * LOG2E;
        }
    }
}

// ---------------- reset progress flags ----------------
__global__ void init_kernel() {
    if (threadIdx.x < NBLK) g_prog[threadIdx.x] = 0;
}

// ---------------- DP wavefront: 4x4 wavefront tiles, hidden staging ---------
__device__ __forceinline__ int ld_acq(const int* p) {
    int v;
    asm volatile("ld.acquire.gpu.u32 %0, [%1];" : "=r"(v) : "l"(p) : "memory");
    return v;
}
__device__ __forceinline__ void st_rel(int* p, int v) {
    asm volatile("st.release.gpu.u32 [%0], %1;" :: "l"(p), "r"(v) : "memory");
}
__device__ __forceinline__ float ex2(float x) {
    float r; asm("ex2.approx.f32 %0, %1;" : "=f"(r) : "f"(x)); return r;
}
__device__ __forceinline__ float lg2(float x) {
    float r; asm("lg2.approx.f32 %0, %1;" : "=f"(r) : "f"(x)); return r;
}

// base-2 softmin cell, 3 MUFU: the min's exp term is exactly 1.
#define CELL(nv, u, d, l, cost) do {                                   \
    float p_ = fminf((u), (d));                                        \
    float q_ = fmaxf((u), (d));                                        \
    float m_ = fminf(p_, (l));                                         \
    float md_ = fmaxf(p_, fminf(q_, (l)));                             \
    float mx_ = fmaxf(q_, (l));                                        \
    float s_ = 1.0f + ex2(m_ - md_) + ex2(m_ - mx_);                   \
    (nv) = (cost) + m_ - lg2(s_);                                      \
} while (0)

__global__ void __launch_bounds__(32, 1) dp_kernel(float* __restrict__ out) {
    __shared__ float tb[2][17];   // double-buffered boundary windows

    const int b = blockIdx.x;
    const int L = threadIdx.x;
    const int row0 = b * 128 + 4 * L;
    const float4* __restrict__ Dr0 = (const float4*)(g_D + (size_t)(row0 + 0) * NN);
    const float4* __restrict__ Dr1 = (const float4*)(g_D + (size_t)(row0 + 1) * NN);
    const float4* __restrict__ Dr2 = (const float4*)(g_D + (size_t)(row0 + 2) * NN);
    const float4* __restrict__ Dr3 = (const float4*)(g_D + (size_t)(row0 + 3) * NN);
    float* mybnd = g_bnd[b];
    const float* upbnd = (b > 0) ? g_bnd[b - 1] : (const float*)0;
    const int* upflag = (b > 0) ? &g_prog[b - 1] : (const int*)0;

    float lft0 = INF_V, lft1 = INF_V, lft2 = INF_V, lft3 = INF_V;
    float bot0 = INF_V, bot1 = INF_V, bot2 = INF_V, bot3 = INF_V;
    float dgv = INF_V;

    int   fc = 0;            // lane-0 cached copy of upstream progress flag
    float pend = INF_V;      // lanes 0..16: next window value (loaded early, STS'd late)

    // ---- prologue (b>0): stage window 0, warm the flag cache ----
    if (b > 0) {
        if (L == 0) { do { fc = ld_acq(upflag); } while (fc < 4); }
        __syncwarp();
        if (L < 17) {
            int col = L - 1;
            tb[0][L] = (col >= 0) ? __ldcg(&upbnd[col]) : INF_V;
        }
        if (L == 0) fc = ld_acq(upflag);    // refresh; used 4 steps later
        __syncwarp();
    }

    float4 c0 = __ldg(Dr0), c1 = __ldg(Dr1), c2 = __ldg(Dr2), c3 = __ldg(Dr3);

    const int TT = NTILE + 31;
    #pragma unroll 1
    for (int tau = 0; tau < TT; tau++) {
        const int j = tau - L;                    // this lane's tile-column

        // ---- group boundary: commit pending window, start loading the next ----
        if (b > 0 && tau < NTILE && (tau & 3) == 0) {
            const int g = tau >> 2;
            __syncwarp();
            if (g >= 1 && L < 17) tb[g & 1][L] = pend;   // window g staged now
            __syncwarp();
            if (tau + 8 <= NTILE) {
                if (L == 0) {
                    int need = tau + 8;                  // tiles for window g+1
                    while (fc < need) fc = ld_acq(upflag);   // usually already true
                }
                __syncwarp();
                if (L < 17) pend = __ldcg(&upbnd[16 * (g + 1) - 1 + L]);
                if (L == 0) fc = ld_acq(upflag);         // refresh, latency hidden
            }
        }

        // ---- prefetch next tile's costs ----
        int jn = j + 1; if (jn < 0) jn = 0; if (jn > NTILE - 1) jn = NTILE - 1;
        float4 p0 = __ldg(Dr0 + jn);
        float4 p1 = __ldg(Dr1 + jn);
        float4 p2 = __ldg(Dr2 + jn);
        float4 p3 = __ldg(Dr3 + jn);

        // ---- top handoff: neighbor's bottom row from previous step ----
        float t0 = __shfl_up_sync(0xffffffffu, bot0, 1);
        float t1 = __shfl_up_sync(0xffffffffu, bot1, 1);
        float t2 = __shfl_up_sync(0xffffffffu, bot2, 1);
        float t3 = __shfl_up_sync(0xffffffffu, bot3, 1);
        if (L == 0) {
            if (b == 0) {
                t0 = t1 = t2 = t3 = INF_V;
                dgv = (tau == 0) ? 0.0f : INF_V;
            } else {
                const float* wb = tb[(tau >> 2) & 1];
                int p = (tau & 3) * 4;
                dgv = wb[p];
                t0 = wb[p + 1]; t1 = wb[p + 2];
                t2 = wb[p + 3]; t3 = wb[p + 4];
            }
        }
        if (j == 0 && L > 0) dgv = INF_V;         // diag of col 0 is dp[.][-1]

        if (j >= 0 && j < NTILE) {
            // 4x4 tile, cells emitted in anti-diagonal (wavefront) order.
            float V00, V01, V02, V03;
            float V10, V11, V12, V13;
            float V20, V21, V22, V23;
            float V30, V31, V32, V33;
            // rank 0
            CELL(V00, t0,  dgv,  lft0, c0.x);
            // rank 1
            CELL(V01, t1,  t0,   V00,  c0.y);
            CELL(V10, V00, lft0, lft1, c1.x);
            // rank 2
            CELL(V02, t2,  t1,   V01,  c0.z);
            CELL(V11, V01, V00,  V10,  c1.y);
            CELL(V20, V10, lft1, lft2, c2.x);
            // rank 3
            CELL(V03, t3,  t2,   V02,  c0.w);
            CELL(V12, V02, V01,  V11,  c1.z);
            CELL(V21, V11, V10,  V20,  c2.y);
            CELL(V30, V20, lft2, lft3, c3.x);
            // rank 4
            CELL(V13, V03, V02,  V12,  c1.w);
            CELL(V22, V12, V11,  V21,  c2.z);
            CELL(V31, V21, V20,  V30,  c3.y);
            // rank 5
            CELL(V23, V13, V12,  V22,  c2.w);
            CELL(V32, V22, V21,  V31,  c3.z);
            // rank 6
            CELL(V33, V23, V22,  V32,  c3.w);

            lft0 = V03; lft1 = V13; lft2 = V23; lft3 = V33;
            bot0 = V30; bot1 = V31; bot2 = V32; bot3 = V33;

            if (L == 31) {
                *(float4*)&mybnd[4 * j] = make_float4(bot0, bot1, bot2, bot3);
                if (b < NBLK - 1)
                    st_rel(&g_prog[b], j + 1);   // publish every tile
            }
        }
        dgv = t3;                                 // diag for next tile = top[3]

        c0 = p0; c1 = p1; c2 = p2; c3 = p3;       // rotate cost buffers
    }

    if (b == NBLK - 1 && L == 31) out[0] = lft3 * LN2;   // dp[4096][4096]
}

extern "C" void kernel_launch(void* const* d_in, const int* in_sizes, int n_in,
                              void* d_out, int out_size) {
    const float* x = (const float*)d_in[0];
    const float* y = (const float*)d_in[1];
    float* out = (float*)d_out;

    norms_kernel<<<(2 * NN * 32) / 256, 256>>>(x, y);
    dim3 gD(NN / 64, NN / 64);
    dim3 bD(16, 16);
    dmat_kernel<<<gD, bD>>>(x, y);
    init_kernel<<<1, NBLK>>>();
    dp_kernel<<<NBLK, 32>>>(out);
}

// round 14
// speedup vs baseline: 1.5279x; 1.5279x over previous
#include <cuda_runtime.h>

#define NN 4096
#define DIM 64
#define INF_V 1e10f
#define NBLK 32           // 32 bands x 128 rows (one warp per band, 4 rows/lane)
#define NTILE 1024        // tile-columns (4 cols each)
#define LOG2E 1.4426950408889634f
#define LN2   0.6931471805599453f

__device__ float g_D[(size_t)NN * NN];    // cost matrix, PRE-SCALED by log2(e)
__device__ float g_xn[NN];
__device__ float g_yn[NN];
__device__ float g_bnd[NBLK][NN];         // bottom boundary row of each band (base-2)
__device__ int   g_prog[NBLK];            // tiles published per band

// ---------------- norms ----------------
__global__ void norms_kernel(const float* __restrict__ x, const float* __restrict__ y) {
    int w = (blockIdx.x * blockDim.x + threadIdx.x) >> 5;
    int lane = threadIdx.x & 31;
    if (w >= 2 * NN) return;
    const float* src = (w < NN) ? x : y;
    int row = (w < NN) ? w : w - NN;
    float a = src[row * DIM + lane];
    float b = src[row * DIM + 32 + lane];
    float s = a * a + b * b;
    #pragma unroll
    for (int o = 16; o; o >>= 1) s += __shfl_xor_sync(0xffffffffu, s, o);
    if (lane == 0) { if (w < NN) g_xn[row] = s; else g_yn[row] = s; }
}

// ---------------- D2 = (|x|^2 + |y|^2 - 2 x.y) * log2(e) ----------------
__global__ void dmat_kernel(const float* __restrict__ x, const float* __restrict__ y) {
    __shared__ float xs[64][65];
    __shared__ float ys[64][65];
    int tx = threadIdx.x, ty = threadIdx.y;
    int tid = ty * 16 + tx;
    int rb = blockIdx.y * 64, cb = blockIdx.x * 64;

    for (int i = tid; i < 64 * 64; i += 256) {
        int rr = i >> 6, kk = i & 63;
        xs[rr][kk] = x[(rb + rr) * DIM + kk];
        ys[rr][kk] = y[(cb + rr) * DIM + kk];
    }
    __syncthreads();

    float acc[4][4] = {};
    #pragma unroll
    for (int k = 0; k < 64; k++) {
        float xv[4], yv[4];
        #pragma unroll
        for (int i = 0; i < 4; i++) xv[i] = xs[ty + 16 * i][k];
        #pragma unroll
        for (int j = 0; j < 4; j++) yv[j] = ys[tx + 16 * j][k];
        #pragma unroll
        for (int i = 0; i < 4; i++)
            #pragma unroll
            for (int j = 0; j < 4; j++)
                acc[i][j] += xv[i] * yv[j];
    }

    #pragma unroll
    for (int i = 0; i < 4; i++) {
        int r = rb + ty + 16 * i;
        float xnr = g_xn[r];
        #pragma unroll
        for (int j = 0; j < 4; j++) {
            int c = cb + tx + 16 * j;
            g_D[(size_t)r * NN + c] = (xnr + g_yn[c] - 2.0f * acc[i][j]) * LOG2E;
        }
    }
}

// ---------------- reset progress flags ----------------
__global__ void init_kernel() {
    if (threadIdx.x < NBLK) g_prog[threadIdx.x] = 0;
}

// ---------------- DP wavefront ----------------
__device__ __forceinline__ int ld_acq(const int* p) {
    int v;
    asm volatile("ld.acquire.gpu.u32 %0, [%1];" : "=r"(v) : "l"(p) : "memory");
    return v;
}
__device__ __forceinline__ void st_rel(int* p, int v) {
    asm volatile("st.release.gpu.u32 [%0], %1;" :: "l"(p), "r"(v) : "memory");
}
__device__ __forceinline__ float ex2(float x) {
    float r; asm("ex2.approx.f32 %0, %1;" : "=f"(r) : "f"(x)); return r;
}
__device__ __forceinline__ float lg2(float x) {
    float r; asm("lg2.approx.f32 %0, %1;" : "=f"(r) : "f"(x)); return r;
}

// base-2 softmin cell, 3 MUFU: the min's exp term is exactly 1.
#define CELL(nv, u, d, l, cost) do {                                   \
    float p_ = fminf((u), (d));                                        \
    float q_ = fmaxf((u), (d));                                        \
    float m_ = fminf(p_, (l));                                         \
    float md_ = fmaxf(p_, fminf(q_, (l)));                             \
    float mx_ = fmaxf(q_, (l));                                        \
    float s_ = 1.0f + ex2(m_ - md_) + ex2(m_ - mx_);                   \
    (nv) = (cost) + m_ - lg2(s_);                                      \
} while (0)

// Full 4x4 tile in wavefront (anti-diagonal) order. Updates lft*/bot* in place.
__device__ __forceinline__ void tile16(
    float t0, float t1, float t2, float t3, float dgv,
    float& lft0, float& lft1, float& lft2, float& lft3,
    float& bot0, float& bot1, float& bot2, float& bot3,
    float4 c0, float4 c1, float4 c2, float4 c3)
{
    float V00, V01, V02, V03, V10, V11, V12, V13;
    float V20, V21, V22, V23, V30, V31, V32, V33;
    CELL(V00, t0,  dgv,  lft0, c0.x);                 // rank 0
    CELL(V01, t1,  t0,   V00,  c0.y);                 // rank 1
    CELL(V10, V00, lft0, lft1, c1.x);
    CELL(V02, t2,  t1,   V01,  c0.z);                 // rank 2
    CELL(V11, V01, V00,  V10,  c1.y);
    CELL(V20, V10, lft1, lft2, c2.x);
    CELL(V03, t3,  t2,   V02,  c0.w);                 // rank 3
    CELL(V12, V02, V01,  V11,  c1.z);
    CELL(V21, V11, V10,  V20,  c2.y);
    CELL(V30, V20, lft2, lft3, c3.x);
    CELL(V13, V03, V02,  V12,  c1.w);                 // rank 4
    CELL(V22, V12, V11,  V21,  c2.z);
    CELL(V31, V21, V20,  V30,  c3.y);
    CELL(V23, V13, V12,  V22,  c2.w);                 // rank 5
    CELL(V32, V22, V21,  V31,  c3.z);
    CELL(V33, V23, V22,  V32,  c3.w);                 // rank 6
    lft0 = V03; lft1 = V13; lft2 = V23; lft3 = V33;
    bot0 = V30; bot1 = V31; bot2 = V32; bot3 = V33;
}

__global__ void __launch_bounds__(32, 1) dp_kernel(float* __restrict__ out) {
    __shared__ float tb[18];

    const int b = blockIdx.x;
    const int L = threadIdx.x;
    const int row0 = b * 128 + 4 * L;
    const float4* __restrict__ Dr0 = (const float4*)(g_D + (size_t)(row0 + 0) * NN);
    const float4* __restrict__ Dr1 = (const float4*)(g_D + (size_t)(row0 + 1) * NN);
    const float4* __restrict__ Dr2 = (const float4*)(g_D + (size_t)(row0 + 2) * NN);
    const float4* __restrict__ Dr3 = (const float4*)(g_D + (size_t)(row0 + 3) * NN);
    float* mybnd = g_bnd[b];
    const float* upbnd = (b > 0) ? g_bnd[b - 1] : (const float*)0;

    float lft0 = INF_V, lft1 = INF_V, lft2 = INF_V, lft3 = INF_V;
    float bot0 = INF_V, bot1 = INF_V, bot2 = INF_V, bot3 = INF_V;
    float dgv = INF_V;

    if (L < 18) tb[L] = INF_V;        // b==0 reads INF through the same path
    __syncwarp();

    float4 c0 = __ldg(Dr0), c1 = __ldg(Dr1), c2 = __ldg(Dr2), c3 = __ldg(Dr3);

    // ================= prologue: tau = 0..31 (generic, R9 body) =================
    #pragma unroll 1
    for (int tau = 0; tau < 32; tau++) {
        const int j = tau - L;
        if (b > 0 && (tau & 3) == 0) {
            if (L == 0) { while (ld_acq(&g_prog[b - 1]) < tau + 4) { } }
            __syncwarp();
            if (L < 17) {
                int col = 4 * tau - 1 + L;
                tb[L] = (col >= 0) ? __ldcg(&upbnd[col]) : INF_V;
            }
            __syncwarp();
        }
        int jn = j + 1; if (jn < 0) jn = 0;
        float4 p0 = __ldg(Dr0 + jn), p1 = __ldg(Dr1 + jn);
        float4 p2 = __ldg(Dr2 + jn), p3 = __ldg(Dr3 + jn);

        float t0 = __shfl_up_sync(0xffffffffu, bot0, 1);
        float t1 = __shfl_up_sync(0xffffffffu, bot1, 1);
        float t2 = __shfl_up_sync(0xffffffffu, bot2, 1);
        float t3 = __shfl_up_sync(0xffffffffu, bot3, 1);
        if (L == 0) {
            if (b == 0) {
                t0 = t1 = t2 = t3 = INF_V;
                dgv = (tau == 0) ? 0.0f : INF_V;
            } else {
                int p = (tau & 3) * 4;
                dgv = tb[p];
                t0 = tb[p + 1]; t1 = tb[p + 2]; t2 = tb[p + 3]; t3 = tb[p + 4];
            }
        }
        if (j == 0 && L > 0) dgv = INF_V;

        if (j >= 0) {
            tile16(t0, t1, t2, t3, dgv, lft0, lft1, lft2, lft3,
                   bot0, bot1, bot2, bot3, c0, c1, c2, c3);
            if (L == 31) {           // only j==0 occurs here; no release yet
                *(float4*)&mybnd[4 * j] = make_float4(bot0, bot1, bot2, bot3);
            }
        }
        dgv = t3;
        c0 = p0; c1 = p1; c2 = p2; c3 = p3;
    }

    // ============ steady: tau = 32..1023, unrolled by group of 4 ============
    // All lanes active (0 < j < NTILE for every lane), no edge branches.
    #pragma unroll 1
    for (int g = 8; g < 256; g++) {
        const int tau0 = 4 * g;
        if (b > 0) {                      // stage window for this group
            if (L == 0) { while (ld_acq(&g_prog[b - 1]) < tau0 + 4) { } }
            __syncwarp();
            if (L < 17) tb[L] = __ldcg(&upbnd[4 * tau0 - 1 + L]);
            __syncwarp();
        }
        #pragma unroll
        for (int P = 0; P < 4; P++) {
            const int tau = tau0 + P;
            const int j = tau - L;
            int jn = j + 1; if (jn > NTILE - 1) jn = NTILE - 1;
            float4 p0 = __ldg(Dr0 + jn), p1 = __ldg(Dr1 + jn);
            float4 p2 = __ldg(Dr2 + jn), p3 = __ldg(Dr3 + jn);

            float t0 = __shfl_up_sync(0xffffffffu, bot0, 1);
            float t1 = __shfl_up_sync(0xffffffffu, bot1, 1);
            float t2 = __shfl_up_sync(0xffffffffu, bot2, 1);
            float t3 = __shfl_up_sync(0xffffffffu, bot3, 1);
            {   // branchless lane-0 edge injection (b==0 window is INF)
                float wd = tb[4 * P + 0], w0 = tb[4 * P + 1], w1 = tb[4 * P + 2];
                float w2 = tb[4 * P + 3], w3 = tb[4 * P + 4];
                bool e = (L == 0);
                dgv = e ? wd : dgv;
                t0 = e ? w0 : t0; t1 = e ? w1 : t1;
                t2 = e ? w2 : t2; t3 = e ? w3 : t3;
            }
            if (b == 0 && L == 0 && P == 0) { /* dgv already INF via window */ }

            tile16(t0, t1, t2, t3, dgv, lft0, lft1, lft2, lft3,
                   bot0, bot1, bot2, bot3, c0, c1, c2, c3);

            if (L == 31) {
                *(float4*)&mybnd[4 * j] = make_float4(bot0, bot1, bot2, bot3);
                if (P == 2 && b < NBLK - 1)        // (j&3)==3 exactly at P==2
                    st_rel(&g_prog[b], j + 1);
            }
            dgv = t3;
            c0 = p0; c1 = p1; c2 = p2; c3 = p3;
        }
    }

    // ================= epilogue: tau = 1024..1054 (generic) =================
    #pragma unroll 1
    for (int tau = NTILE; tau < NTILE + 31; tau++) {
        const int j = tau - L;
        int jn = j + 1; if (jn > NTILE - 1) jn = NTILE - 1;
        float4 p0 = __ldg(Dr0 + jn), p1 = __ldg(Dr1 + jn);
        float4 p2 = __ldg(Dr2 + jn), p3 = __ldg(Dr3 + jn);

        float t0 = __shfl_up_sync(0xffffffffu, bot0, 1);
        float t1 = __shfl_up_sync(0xffffffffu, bot1, 1);
        float t2 = __shfl_up_sync(0xffffffffu, bot2, 1);
        float t3 = __shfl_up_sync(0xffffffffu, bot3, 1);

        if (j < NTILE) {
            tile16(t0, t1, t2, t3, dgv, lft0, lft1, lft2, lft3,
                   bot0, bot1, bot2, bot3, c0, c1, c2, c3);
            if (L == 31) {
                *(float4*)&mybnd[4 * j] = make_float4(bot0, bot1, bot2, bot3);
                if ((j & 3) == 3 && b < NBLK - 1)
                    st_rel(&g_prog[b], j + 1);
            }
        }
        dgv = t3;
        c0 = p0; c1 = p1; c2 = p2; c3 = p3;
    }

    if (b == NBLK - 1 && L == 31) out[0] = lft3 * LN2;   // dp[4096][4096]
}

extern "C" void kernel_launch(void* const* d_in, const int* in_sizes, int n_in,
                              void* d_out, int out_size) {
    const float* x = (const float*)d_in[0];
    const float* y = (const float*)d_in[1];
    float* out = (float*)d_out;

    norms_kernel<<<(2 * NN * 32) / 256, 256>>>(x, y);
    dim3 gD(NN / 64, NN / 64);
    dim3 bD(16, 16);
    dmat_kernel<<<gD, bD>>>(x, y);
    init_kernel<<<1, NBLK>>>();
    dp_kernel<<<NBLK, 32>>>(out);
}

// round 15
// speedup vs baseline: 3.1852x; 2.0847x over previous
#include <cuda_runtime.h>

#define NN 4096
#define DIM 64
#define INF_V 1e10f
#define NBLK 32           // 32 bands x 128 rows (one warp per band, 4 rows/lane)
#define NTILE 1024        // tile-columns (4 cols each)
#define LOG2E 1.4426950408889634f
#define LN2   0.6931471805599453f

__device__ float g_D[(size_t)NN * NN];    // cost matrix, PRE-SCALED by log2(e)
__device__ float g_xn[NN];
__device__ float g_yn[NN];
__device__ float g_bnd[NBLK][NN];         // bottom boundary row of each band (base-2)
__device__ int   g_prog[NBLK];            // tiles published per band

// ---------------- norms ----------------
__global__ void norms_kernel(const float* __restrict__ x, const float* __restrict__ y) {
    int w = (blockIdx.x * blockDim.x + threadIdx.x) >> 5;
    int lane = threadIdx.x & 31;
    if (w >= 2 * NN) return;
    const float* src = (w < NN) ? x : y;
    int row = (w < NN) ? w : w - NN;
    float a = src[row * DIM + lane];
    float b = src[row * DIM + 32 + lane];
    float s = a * a + b * b;
    #pragma unroll
    for (int o = 16; o; o >>= 1) s += __shfl_xor_sync(0xffffffffu, s, o);
    if (lane == 0) { if (w < NN) g_xn[row] = s; else g_yn[row] = s; }
}

// ---------------- D2 = (|x|^2 + |y|^2 - 2 x.y) * log2(e) ----------------
__global__ void dmat_kernel(const float* __restrict__ x, const float* __restrict__ y) {
    __shared__ float xs[64][65];
    __shared__ float ys[64][65];
    int tx = threadIdx.x, ty = threadIdx.y;
    int tid = ty * 16 + tx;
    int rb = blockIdx.y * 64, cb = blockIdx.x * 64;

    for (int i = tid; i < 64 * 64; i += 256) {
        int rr = i >> 6, kk = i & 63;
        xs[rr][kk] = x[(rb + rr) * DIM + kk];
        ys[rr][kk] = y[(cb + rr) * DIM + kk];
    }
    __syncthreads();

    float acc[4][4] = {};
    #pragma unroll
    for (int k = 0; k < 64; k++) {
        float xv[4], yv[4];
        #pragma unroll
        for (int i = 0; i < 4; i++) xv[i] = xs[ty + 16 * i][k];
        #pragma unroll
        for (int j = 0; j < 4; j++) yv[j] = ys[tx + 16 * j][k];
        #pragma unroll
        for (int i = 0; i < 4; i++)
            #pragma unroll
            for (int j = 0; j < 4; j++)
                acc[i][j] += xv[i] * yv[j];
    }

    #pragma unroll
    for (int i = 0; i < 4; i++) {
        int r = rb + ty + 16 * i;
        float xnr = g_xn[r];
        #pragma unroll
        for (int j = 0; j < 4; j++) {
            int c = cb + tx + 16 * j;
            g_D[(size_t)r * NN + c] = (xnr + g_yn[c] - 2.0f * acc[i][j]) * LOG2E;
        }
    }
}

// ---------------- reset progress flags ----------------
__global__ void init_kernel() {
    if (threadIdx.x < NBLK) g_prog[threadIdx.x] = 0;
}

// ---------------- DP wavefront ----------------
__device__ __forceinline__ int ld_acq(const int* p) {
    int v;
    asm volatile("ld.acquire.gpu.u32 %0, [%1];" : "=r"(v) : "l"(p) : "memory");
    return v;
}
__device__ __forceinline__ void st_rel(int* p, int v) {
    asm volatile("st.release.gpu.u32 [%0], %1;" :: "l"(p), "r"(v) : "memory");
}
__device__ __forceinline__ float ex2(float x) {
    float r; asm("ex2.approx.f32 %0, %1;" : "=f"(r) : "f"(x)); return r;
}
__device__ __forceinline__ float lg2(float x) {
    float r; asm("lg2.approx.f32 %0, %1;" : "=f"(r) : "f"(x)); return r;
}

// base-2 softmin cell, 3 MUFU: the min's exp term is exactly 1.
#define CELL(nv, u, d, l, cost) do {                                   \
    float p_ = fminf((u), (d));                                        \
    float q_ = fmaxf((u), (d));                                        \
    float m_ = fminf(p_, (l));                                         \
    float md_ = fmaxf(p_, fminf(q_, (l)));                             \
    float mx_ = fmaxf(q_, (l));                                        \
    float s_ = 1.0f + ex2(m_ - md_) + ex2(m_ - mx_);                   \
    (nv) = (cost) + m_ - lg2(s_);                                      \
} while (0)

__global__ void __launch_bounds__(32, 1) dp_kernel(float* __restrict__ out) {
    __shared__ float tb[18];

    const int b = blockIdx.x;
    const int L = threadIdx.x;
    const int row0 = b * 128 + 4 * L;
    const float4* __restrict__ Dr0 = (const float4*)(g_D + (size_t)(row0 + 0) * NN);
    const float4* __restrict__ Dr1 = (const float4*)(g_D + (size_t)(row0 + 1) * NN);
    const float4* __restrict__ Dr2 = (const float4*)(g_D + (size_t)(row0 + 2) * NN);
    const float4* __restrict__ Dr3 = (const float4*)(g_D + (size_t)(row0 + 3) * NN);
    float* mybnd = g_bnd[b];
    const float* upbnd = (b > 0) ? g_bnd[b - 1] : (const float*)0;

    float lft0 = INF_V, lft1 = INF_V, lft2 = INF_V, lft3 = INF_V;
    float bot0 = INF_V, bot1 = INF_V, bot2 = INF_V, bot3 = INF_V;
    float nt0 = INF_V, nt1 = INF_V, nt2 = INF_V, nt3 = INF_V;  // pre-shfl'd top row
    float dgv = INF_V;
    float wtd = INF_V, wt0 = INF_V, wt1 = INF_V, wt2 = INF_V, wt3 = INF_V; // window regs

    if (L < 18) tb[L] = INF_V;        // b==0 (and stale phases) read INF
    __syncwarp();

    float4 c0 = __ldg(Dr0), c1 = __ldg(Dr1), c2 = __ldg(Dr2), c3 = __ldg(Dr3);

    const int TT = NTILE + 31;
    #pragma unroll 1
    for (int tau = 0; tau < TT; tau++) {
        const int j = tau - L;                    // this lane's tile-column

        // ---- stage boundary window every 4 tiles (R4/R9 protocol, verbatim) ----
        if (b > 0 && tau < NTILE && (tau & 3) == 0) {
            if (L == 0) { while (ld_acq(&g_prog[b - 1]) < tau + 4) { } }
            __syncwarp();
            if (L < 17) {
                int col = 4 * tau - 1 + L;
                tb[L] = (col >= 0) ? __ldcg(&upbnd[col]) : INF_V;
            }
            __syncwarp();
        }
        if ((tau & 3) == 0) {                     // phase-0 window into registers
            wtd = tb[0]; wt0 = tb[1]; wt1 = tb[2]; wt2 = tb[3]; wt3 = tb[4];
        }

        // ---- prefetch next tile's costs ----
        int jn = j + 1; if (jn < 0) jn = 0; if (jn > NTILE - 1) jn = NTILE - 1;
        float4 p0 = __ldg(Dr0 + jn);
        float4 p1 = __ldg(Dr1 + jn);
        float4 p2 = __ldg(Dr2 + jn);
        float4 p3 = __ldg(Dr3 + jn);

        // ---- top row: shfl results from previous step + lane-0 edge injection ----
        float t0 = nt0, t1 = nt1, t2 = nt2, t3 = nt3;
        {
            bool e = (L == 0);
            float dsel = (b == 0 && tau == 0) ? 0.0f : wtd;   // dp[0][0] seed
            dgv = e ? dsel : dgv;
            t0 = e ? wt0 : t0; t1 = e ? wt1 : t1;
            t2 = e ? wt2 : t2; t3 = e ? wt3 : t3;
        }
        dgv = (j == 0 && L > 0) ? INF_V : dgv;    // diag of col 0 is dp[.][-1]

        const bool act = (j >= 0) && (j < NTILE);

        // ---- 4x4 tile, wavefront order; shfls issued as soon as V3k exists ----
        float V00, V01, V02, V03, V10, V11, V12, V13;
        float V20, V21, V22, V23, V30, V31, V32, V33;
        CELL(V00, t0,  dgv,  lft0, c0.x);                 // rank 0
        CELL(V01, t1,  t0,   V00,  c0.y);                 // rank 1
        CELL(V10, V00, lft0, lft1, c1.x);
        CELL(V02, t2,  t1,   V01,  c0.z);                 // rank 2
        CELL(V11, V01, V00,  V10,  c1.y);
        CELL(V20, V10, lft1, lft2, c2.x);
        CELL(V03, t3,  t2,   V02,  c0.w);                 // rank 3
        CELL(V12, V02, V01,  V11,  c1.z);
        CELL(V21, V11, V10,  V20,  c2.y);
        CELL(V30, V20, lft2, lft3, c3.x);
        bot0 = act ? V30 : bot0;
        nt0 = __shfl_up_sync(0xffffffffu, bot0, 1);       // overlaps ranks 4-6
        CELL(V13, V03, V02,  V12,  c1.w);                 // rank 4
        CELL(V22, V12, V11,  V21,  c2.z);
        CELL(V31, V21, V20,  V30,  c3.y);
        bot1 = act ? V31 : bot1;
        nt1 = __shfl_up_sync(0xffffffffu, bot1, 1);
        CELL(V23, V13, V12,  V22,  c2.w);                 // rank 5
        CELL(V32, V22, V21,  V31,  c3.z);
        bot2 = act ? V32 : bot2;
        nt2 = __shfl_up_sync(0xffffffffu, bot2, 1);
        CELL(V33, V23, V22,  V32,  c3.w);                 // rank 6
        bot3 = act ? V33 : bot3;
        nt3 = __shfl_up_sync(0xffffffffu, bot3, 1);

        lft0 = act ? V03 : lft0; lft1 = act ? V13 : lft1;
        lft2 = act ? V23 : lft2; lft3 = act ? V33 : lft3;

        // ---- window prefetch for next phase (1..3); phase 0 loads after staging ----
        {
            int phn = (tau + 1) & 3;
            if (phn != 0) {                       // uniform branch
                int q = 4 * phn;
                wtd = tb[q]; wt0 = tb[q + 1]; wt1 = tb[q + 2];
                wt2 = tb[q + 3]; wt3 = tb[q + 4];
            }
        }

        // ---- publish (lane 31 only; R9 granularity) ----
        if (L == 31 && act) {
            *(float4*)&mybnd[4 * j] = make_float4(bot0, bot1, bot2, bot3);
            if ((j & 3) == 3 && b < NBLK - 1)
                st_rel(&g_prog[b], j + 1);        // release orders mybnd stores
        }
        dgv = t3;                                 // diag for next tile = top[3]

        c0 = p0; c1 = p1; c2 = p2; c3 = p3;       // rotate cost buffers
    }

    if (b == NBLK - 1 && L == 31) out[0] = lft3 * LN2;   // dp[4096][4096]
}

extern "C" void kernel_launch(void* const* d_in, const int* in_sizes, int n_in,
                              void* d_out, int out_size) {
    const float* x = (const float*)d_in[0];
    const float* y = (const float*)d_in[1];
    float* out = (float*)d_out;

    norms_kernel<<<(2 * NN * 32) / 256, 256>>>(x, y);
    dim3 gD(NN / 64, NN / 64);
    dim3 bD(16, 16);
    dmat_kernel<<<gD, bD>>>(x, y);
    init_kernel<<<1, NBLK>>>();
    dp_kernel<<<NBLK, 32>>>(out);
}